// round 11
// baseline (speedup 1.0000x reference)
#include <cuda_runtime.h>
#include <cuda_bf16.h>
#include <cstdint>

#define BATCH 8
#define SEQ   2048
#define DIM   64
#define PAIR_BASE 20000
#define SR2   40            // bf16 smem row pitch per 32-K chunk (32 + 8 pad)
#define TOTAL_BLOCKS (16 * 16 * 9)

// ---------------- device scratch (static globals: allocation-free) ----------
__device__ __nv_bfloat16 g_ub[BATCH][SEQ][DIM];   // compacted tf rows, bf16
__device__ __nv_bfloat16 g_vb[BATCH][SEQ][DIM];   // compacted active cols, bf16
__device__ int      g_row_src[BATCH][SEQ];
__device__ int      g_col_src[BATCH][SEQ];
__device__ int      g_row_id[BATCH][SEQ];
__device__ unsigned g_chead[BATCH][PAIR_BASE];    // epoch-tagged: (epoch<<12)|(idx+1)
__device__ unsigned g_cnext[BATCH][SEQ];          // epoch-tagged next
__device__ int      g_nrows[BATCH];               // zero at load; reset by last block
__device__ int      g_ncols[BATCH];
__device__ double   g_numer;                      // zero at load; reset by last block
__device__ unsigned g_epoch = 1;                  // bumped by last block each launch
__device__ unsigned g_done  = 0;                  // completion counter

__device__ __forceinline__ uint32_t smem_u32(const void* p) {
    uint32_t a;
    asm("{ .reg .u64 t; cvta.to.shared.u64 t, %1; cvt.u32.u64 %0, t; }" : "=r"(a) : "l"(p));
    return a;
}
__device__ __forceinline__ void ldmatrix_x4(uint32_t* r, uint32_t addr) {
    asm volatile("ldmatrix.sync.aligned.m8n8.x4.shared.b16 {%0,%1,%2,%3}, [%4];"
        : "=r"(r[0]), "=r"(r[1]), "=r"(r[2]), "=r"(r[3]) : "r"(addr));
}
// NON-trans x2: with B stored [n][k], lane l gets Bmem[row=l/4][col=(l%4)*2+e]
// == exactly the mma.m16n8k16 col-major B fragment (n=t/4, k=(t%4)*2+e).
__device__ __forceinline__ void ldmatrix_x2(uint32_t* r, uint32_t addr) {
    asm volatile("ldmatrix.sync.aligned.m8n8.x2.shared.b16 {%0,%1}, [%2];"
        : "=r"(r[0]), "=r"(r[1]) : "r"(addr));
}
__device__ __forceinline__ void mma_bf16(float* c, const uint32_t* a, const uint32_t* b) {
    asm volatile("mma.sync.aligned.m16n8k16.row.col.f32.bf16.bf16.f32 "
        "{%0,%1,%2,%3}, {%4,%5,%6,%7}, {%8,%9}, {%0,%1,%2,%3};"
        : "+f"(c[0]), "+f"(c[1]), "+f"(c[2]), "+f"(c[3])
        : "r"(a[0]), "r"(a[1]), "r"(a[2]), "r"(a[3]), "r"(b[0]), "r"(b[1]));
}
__device__ __forceinline__ unsigned packbf2(float x, float y) {
    __nv_bfloat162 w = __floats2bfloat162_rn(x, y);
    return *(unsigned*)&w;
}

// ---------------- prep: compaction + bf16 copy + epoch-tagged chains ---------
__global__ void prep_kernel(const int* __restrict__ ids,
                            const unsigned char* __restrict__ tf,
                            const unsigned char* __restrict__ act,
                            const float* __restrict__ u,
                            const float* __restrict__ v) {
    const int b  = blockIdx.x >> 3;
    const int s  = ((blockIdx.x & 7) << 8) + threadIdx.x;
    const int gs = b * SEQ + s;
    const int id = ids[gs];
    const unsigned lane = threadIdx.x & 31;
    const unsigned below = (1u << lane) - 1u;
    const unsigned epoch = g_epoch;

    const bool ht = tf[gs] != 0;
    const unsigned mt = __ballot_sync(0xffffffffu, ht);
    int baset = 0;
    if (lane == 0 && mt) baset = atomicAdd(&g_nrows[b], __popc(mt));
    baset = __shfl_sync(0xffffffffu, baset, 0);
    if (ht) {
        int i = baset + __popc(mt & below);
        g_row_src[b][i] = s;
        g_row_id[b][i]  = id;
        const float4* src = (const float4*)(u + (size_t)gs * DIM);
        uint4* dst = (uint4*)(&g_ub[b][i][0]);
        #pragma unroll
        for (int q = 0; q < 8; q++) {
            float4 a0 = src[2*q], a1 = src[2*q + 1];
            uint4 o;
            o.x = packbf2(a0.x, a0.y); o.y = packbf2(a0.z, a0.w);
            o.z = packbf2(a1.x, a1.y); o.w = packbf2(a1.z, a1.w);
            dst[q] = o;
        }
    }

    const bool ha = act[gs] != 0;
    const unsigned ma = __ballot_sync(0xffffffffu, ha);
    int basea = 0;
    if (lane == 0 && ma) basea = atomicAdd(&g_ncols[b], __popc(ma));
    basea = __shfl_sync(0xffffffffu, basea, 0);
    if (ha) {
        int i = basea + __popc(ma & below);
        g_col_src[b][i] = s;
        g_cnext[b][i]   = atomicExch(&g_chead[b][id], (epoch << 12) | (unsigned)(i + 1));
        const float4* src = (const float4*)(v + (size_t)gs * DIM);
        uint4* dst = (uint4*)(&g_vb[b][i][0]);
        #pragma unroll
        for (int q = 0; q < 8; q++) {
            float4 a0 = src[2*q], a1 = src[2*q + 1];
            uint4 o;
            o.x = packbf2(a0.x, a0.y); o.y = packbf2(a0.z, a0.w);
            o.z = packbf2(a1.x, a1.y); o.w = packbf2(a1.z, a1.w);
            dst[q] = o;
        }
    }
}

// ---------------- main: correction (z==0) + bf16 HMMA (z>=1) + finalize tail -
__global__ __launch_bounds__(256, 2)
void main_kernel(const float* __restrict__ u, const float* __restrict__ v,
                 const int* __restrict__ keys, int M,
                 float* __restrict__ out, int n_out) {
    __shared__ __align__(16) __nv_bfloat16 sAh[128 * SR2];
    __shared__ __align__(16) __nv_bfloat16 sBh[128 * SR2];
    __shared__ float wsum[8];
    __shared__ unsigned s_last;
    __shared__ double s_res;

    const int tid  = threadIdx.x;
    const int wid  = tid >> 5;
    const int lane = tid & 31;

    if (blockIdx.z == 0) {
        // ---------- correction: rare positives get [-log p + log(1-p)] ----------
        const int cb    = blockIdx.y * 16 + blockIdx.x;   // 0..255
        const int b     = cb & 7;
        const int chunk = cb >> 3;                        // 0..31
        const int nr    = g_nrows[b];
        const int r     = chunk + (tid << 5);
        const unsigned epoch = g_epoch;
        float corr = 0.f;
        if (r < nr) {
            const int rid    = g_row_id[b][r];
            const int lo_key = rid * PAIR_BASE;
            const int hi_key = lo_key + PAIR_BASE;
            int lo = 0, hi = M;
            while (lo < hi) {
                int mid = (lo + hi) >> 1;
                if (__ldg(&keys[mid]) < lo_key) lo = mid + 1; else hi = mid;
            }
            const float* ur = u + ((size_t)(b * SEQ + g_row_src[b][r])) * DIM;
            int prev = -1;
            for (int i = lo; i < M; i++) {
                const int k = __ldg(&keys[i]);
                if (k >= hi_key) break;
                if (k == prev) continue;     // set semantics (duplicate keys)
                prev = k;
                unsigned c = g_chead[b][k - lo_key];
                while ((c >> 12) == epoch) {   // stale-epoch value terminates chain
                    const int ci = (int)(c & 0xFFFu) - 1;
                    const float* vc = v + ((size_t)(b * SEQ + g_col_src[b][ci])) * DIM;
                    float p = 0.f;
                    #pragma unroll
                    for (int q = 0; q < DIM; q++) p = fmaf(ur[q], vc[q], p);
                    p = fminf(fmaxf(p, 1e-8f), 1.0f - 1e-8f);
                    corr += __logf(1.0f - p) - __logf(p);
                    c = g_cnext[b][ci];
                }
            }
        }
        #pragma unroll
        for (int o = 16; o; o >>= 1) corr += __shfl_xor_sync(0xffffffffu, corr, o);
        if ((tid & 31) == 0 && corr != 0.f) atomicAdd(&g_numer, (double)corr);
    } else {
        // ---------- GEMM path: 128x128 tile, single-pass bf16 mma.sync ----------
        const int b    = blockIdx.z - 1;
        const int nr   = g_nrows[b];
        const int nc   = g_ncols[b];
        const int row0 = blockIdx.y * 128;
        const int col0 = blockIdx.x * 128;
        if (row0 < nr && col0 < nc) {
            // warp tiling: 2 (M) x 4 (N) warps; warp tile 64x32
            const int wm = wid & 1, wn = wid >> 1;
            const int m_base = wm * 64, n_base = wn * 32;

            const uint32_t aH = smem_u32(sAh) +
                (uint32_t)(((m_base + (lane & 15)) * SR2 + ((lane >> 4) << 3)) * 2);
            const uint32_t bH = smem_u32(sBh) +
                (uint32_t)(((n_base + (lane & 7)) * SR2 + (((lane >> 3) & 1) << 3)) * 2);

            // staging: bf16 direct copy (rows compacted & contiguous)
            const int rr = tid >> 1;
            const int hf = (tid & 1) << 4;   // 0 or 16 bf16 within 32-chunk
            const __nv_bfloat16* uR = &g_ub[b][row0 + rr][hf];
            const __nv_bfloat16* vR = &g_vb[b][col0 + rr][hf];

            float acc[4][4][4];
            #pragma unroll
            for (int mi = 0; mi < 4; mi++)
                #pragma unroll
                for (int ni = 0; ni < 4; ni++)
                    #pragma unroll
                    for (int q = 0; q < 4; q++) acc[mi][ni][q] = 0.f;

            #pragma unroll
            for (int kc = 0; kc < 2; kc++) {
                {
                    const int base = rr * SR2 + hf;
                    ((uint4*)(&sAh[base]))[0] = ((const uint4*)(uR + kc * 32))[0];
                    ((uint4*)(&sAh[base]))[1] = ((const uint4*)(uR + kc * 32))[1];
                    ((uint4*)(&sBh[base]))[0] = ((const uint4*)(vR + kc * 32))[0];
                    ((uint4*)(&sBh[base]))[1] = ((const uint4*)(vR + kc * 32))[1];
                }
                __syncthreads();

                #pragma unroll
                for (int kk = 0; kk < 2; kk++) {
                    const uint32_t koff = (uint32_t)(kk * 16 * 2);
                    uint32_t ah[4][4], bh[4][2];
                    #pragma unroll
                    for (int mi = 0; mi < 4; mi++)
                        ldmatrix_x4(ah[mi], aH + (uint32_t)((mi * 16 * SR2) * 2) + koff);
                    #pragma unroll
                    for (int ni = 0; ni < 4; ni++)
                        ldmatrix_x2(bh[ni], bH + (uint32_t)((ni * 8 * SR2) * 2) + koff);
                    #pragma unroll
                    for (int mi = 0; mi < 4; mi++)
                        #pragma unroll
                        for (int ni = 0; ni < 4; ni++)
                            mma_bf16(acc[mi][ni], ah[mi], bh[ni]);
                }
                __syncthreads();
            }

            // ---- epilogue: -log(1-p) over valid pairs, 8 values per __logf ----
            const int rq = lane >> 2;
            const int cq = (lane & 3) << 1;
            float lsum = 0.f;
            #pragma unroll
            for (int mi = 0; mi < 4; mi++) {
                const int rA = row0 + m_base + mi * 16 + rq;
                #pragma unroll
                for (int np = 0; np < 2; np++) {
                    float prod = 1.0f;
                    #pragma unroll
                    for (int nj = 0; nj < 2; nj++) {
                        const int ni = np * 2 + nj;
                        const int cA = col0 + n_base + ni * 8 + cq;
                        #pragma unroll
                        for (int q = 0; q < 4; q++) {
                            const int r = rA + ((q >> 1) << 3);
                            const int c = cA + (q & 1);
                            float p = acc[mi][ni][q];
                            p = fminf(fmaxf(p, 1e-8f), 1.0f - 1e-8f);
                            const float x = (r < nr && c < nc) ? (1.0f - p) : 1.0f;
                            prod *= x;
                        }
                    }
                    lsum -= __logf(prod);
                }
            }
            #pragma unroll
            for (int o = 16; o; o >>= 1) lsum += __shfl_xor_sync(0xffffffffu, lsum, o);
            if (lane == 0) wsum[wid] = lsum;
            __syncthreads();
            if (wid == 0) {
                float s = (lane < 8) ? wsum[lane] : 0.f;
                #pragma unroll
                for (int o = 4; o; o >>= 1) s += __shfl_xor_sync(0xffffffffu, s, o);
                if (lane == 0) atomicAdd(&g_numer, (double)s);
            }
        }
    }

    // ---------- common tail: last block finalizes ----------
    __threadfence();
    if (tid == 0) {
        unsigned t = atomicAdd(&g_done, 1u);
        s_last = (t == TOTAL_BLOCKS - 1) ? 1u : 0u;
    }
    __syncthreads();
    if (s_last) {
        if (tid == 0) {
            __threadfence();
            double denom = 0.0;
            #pragma unroll
            for (int q = 0; q < BATCH; q++)
                denom += (double)g_nrows[q] * (double)g_ncols[q];
            s_res = g_numer / (denom + 1e-8);
            g_numer = 0.0;
            #pragma unroll
            for (int q = 0; q < BATCH; q++) { g_nrows[q] = 0; g_ncols[q] = 0; }
            g_epoch = g_epoch + 1;
            g_done  = 0;
        }
        __syncthreads();
        float r = (float)s_res;
        for (int i = tid; i < n_out; i += blockDim.x) out[i] = r;
    }
}

// ---------------- launch ------------------------------------------------------
extern "C" void kernel_launch(void* const* d_in, const int* in_sizes, int n_in,
                              void* d_out, int out_size) {
    const int*           ids  = (const int*)d_in[0];
    const unsigned char* tf   = (const unsigned char*)d_in[1];
    const unsigned char* act  = (const unsigned char*)d_in[2];
    const int*           keys = (const int*)d_in[3];
    const float*         u    = (const float*)d_in[4];
    const float*         v    = (const float*)d_in[5];
    const int M = in_sizes[3];

    prep_kernel<<<64, 256>>>(ids, tf, act, u, v);
    dim3 grid(SEQ / 128, SEQ / 128, BATCH + 1);   // z==0 -> correction blocks
    main_kernel<<<grid, 256>>>(u, v, keys, M, (float*)d_out, out_size);
}

// round 12
// speedup vs baseline: 1.1576x; 1.1576x over previous
#include <cuda_runtime.h>
#include <cuda_bf16.h>
#include <cstdint>

#define BATCH 8
#define SEQ   2048
#define DIM   64
#define PAIR_BASE 20000
#define SR2   40            // bf16 smem row pitch per 32-K chunk (32 + 8 pad)

// ---------------- device scratch (static globals: allocation-free) ----------
__device__ __nv_bfloat16 g_ub[BATCH][SEQ][DIM];   // compacted tf rows, bf16
__device__ __nv_bfloat16 g_vb[BATCH][SEQ][DIM];   // compacted active cols, bf16
__device__ int      g_row_src[BATCH][SEQ];
__device__ int      g_col_src[BATCH][SEQ];
__device__ int      g_row_id[BATCH][SEQ];
__device__ unsigned g_chead[BATCH][PAIR_BASE];    // epoch-tagged: (epoch<<12)|(idx+1)
__device__ unsigned g_cnext[BATCH][SEQ];          // epoch-tagged next
__device__ int      g_nrows[BATCH];               // zero at load; reset by finalize
__device__ int      g_ncols[BATCH];
__device__ double   g_numer;                      // zero at load; reset by finalize
__device__ unsigned g_epoch = 1;                  // bumped by finalize each launch

__device__ __forceinline__ uint32_t smem_u32(const void* p) {
    uint32_t a;
    asm("{ .reg .u64 t; cvta.to.shared.u64 t, %1; cvt.u32.u64 %0, t; }" : "=r"(a) : "l"(p));
    return a;
}
__device__ __forceinline__ void ldmatrix_x4(uint32_t* r, uint32_t addr) {
    asm volatile("ldmatrix.sync.aligned.m8n8.x4.shared.b16 {%0,%1,%2,%3}, [%4];"
        : "=r"(r[0]), "=r"(r[1]), "=r"(r[2]), "=r"(r[3]) : "r"(addr));
}
// NON-trans x2: with B stored [n][k], lane l gets Bmem[row=l/4][col=(l%4)*2+e]
// == exactly the mma.m16n8k16 col-major B fragment (n=t/4, k=(t%4)*2+e).
__device__ __forceinline__ void ldmatrix_x2(uint32_t* r, uint32_t addr) {
    asm volatile("ldmatrix.sync.aligned.m8n8.x2.shared.b16 {%0,%1}, [%2];"
        : "=r"(r[0]), "=r"(r[1]) : "r"(addr));
}
__device__ __forceinline__ void mma_bf16(float* c, const uint32_t* a, const uint32_t* b) {
    asm volatile("mma.sync.aligned.m16n8k16.row.col.f32.bf16.bf16.f32 "
        "{%0,%1,%2,%3}, {%4,%5,%6,%7}, {%8,%9}, {%0,%1,%2,%3};"
        : "+f"(c[0]), "+f"(c[1]), "+f"(c[2]), "+f"(c[3])
        : "r"(a[0]), "r"(a[1]), "r"(a[2]), "r"(a[3]), "r"(b[0]), "r"(b[1]));
}
__device__ __forceinline__ unsigned packbf2(float x, float y) {
    __nv_bfloat162 w = __floats2bfloat162_rn(x, y);
    return *(unsigned*)&w;
}

// ---------------- prep: compaction + bf16 copy + epoch-tagged chains ---------
__global__ void prep_kernel(const int* __restrict__ ids,
                            const unsigned char* __restrict__ tf,
                            const unsigned char* __restrict__ act,
                            const float* __restrict__ u,
                            const float* __restrict__ v) {
    const int b  = blockIdx.x >> 3;
    const int s  = ((blockIdx.x & 7) << 8) + threadIdx.x;
    const int gs = b * SEQ + s;
    const int id = ids[gs];
    const unsigned lane = threadIdx.x & 31;
    const unsigned below = (1u << lane) - 1u;
    const unsigned epoch = g_epoch;

    const bool ht = tf[gs] != 0;
    const unsigned mt = __ballot_sync(0xffffffffu, ht);
    int baset = 0;
    if (lane == 0 && mt) baset = atomicAdd(&g_nrows[b], __popc(mt));
    baset = __shfl_sync(0xffffffffu, baset, 0);
    if (ht) {
        int i = baset + __popc(mt & below);
        g_row_src[b][i] = s;
        g_row_id[b][i]  = id;
        const float4* src = (const float4*)(u + (size_t)gs * DIM);
        uint4* dst = (uint4*)(&g_ub[b][i][0]);
        #pragma unroll
        for (int q = 0; q < 8; q++) {
            float4 a0 = src[2*q], a1 = src[2*q + 1];
            uint4 o;
            o.x = packbf2(a0.x, a0.y); o.y = packbf2(a0.z, a0.w);
            o.z = packbf2(a1.x, a1.y); o.w = packbf2(a1.z, a1.w);
            dst[q] = o;
        }
    }

    const bool ha = act[gs] != 0;
    const unsigned ma = __ballot_sync(0xffffffffu, ha);
    int basea = 0;
    if (lane == 0 && ma) basea = atomicAdd(&g_ncols[b], __popc(ma));
    basea = __shfl_sync(0xffffffffu, basea, 0);
    if (ha) {
        int i = basea + __popc(ma & below);
        g_col_src[b][i] = s;
        g_cnext[b][i]   = atomicExch(&g_chead[b][id], (epoch << 12) | (unsigned)(i + 1));
        const float4* src = (const float4*)(v + (size_t)gs * DIM);
        uint4* dst = (uint4*)(&g_vb[b][i][0]);
        #pragma unroll
        for (int q = 0; q < 8; q++) {
            float4 a0 = src[2*q], a1 = src[2*q + 1];
            uint4 o;
            o.x = packbf2(a0.x, a0.y); o.y = packbf2(a0.z, a0.w);
            o.z = packbf2(a1.x, a1.y); o.w = packbf2(a1.z, a1.w);
            dst[q] = o;
        }
    }
}

// ---------------- main: correction (z==0) + bf16 HMMA GEMM (z>=1) -----------
__global__ __launch_bounds__(256, 2)
void main_kernel(const float* __restrict__ u, const float* __restrict__ v,
                 const int* __restrict__ keys, int M) {
    __shared__ __align__(16) __nv_bfloat16 sAh[128 * SR2];
    __shared__ __align__(16) __nv_bfloat16 sBh[128 * SR2];
    __shared__ float wsum[8];

    const int tid  = threadIdx.x;
    const int wid  = tid >> 5;
    const int lane = tid & 31;

    if (blockIdx.z == 0) {
        // ---------- correction: rare positives get [-log p + log(1-p)] ----------
        const int cb    = blockIdx.y * 16 + blockIdx.x;   // 0..255
        const int b     = cb & 7;
        const int chunk = cb >> 3;                        // 0..31
        const int nr    = g_nrows[b];
        const int r     = chunk + (tid << 5);
        const unsigned epoch = g_epoch;
        float corr = 0.f;
        if (r < nr) {
            const int rid    = g_row_id[b][r];
            const int lo_key = rid * PAIR_BASE;
            const int hi_key = lo_key + PAIR_BASE;
            int lo = 0, hi = M;
            while (lo < hi) {
                int mid = (lo + hi) >> 1;
                if (__ldg(&keys[mid]) < lo_key) lo = mid + 1; else hi = mid;
            }
            const float* ur = u + ((size_t)(b * SEQ + g_row_src[b][r])) * DIM;
            int prev = -1;
            for (int i = lo; i < M; i++) {
                const int k = __ldg(&keys[i]);
                if (k >= hi_key) break;
                if (k == prev) continue;     // set semantics (duplicate keys)
                prev = k;
                unsigned c = g_chead[b][k - lo_key];
                while ((c >> 12) == epoch) {   // stale-epoch value terminates chain
                    const int ci = (int)(c & 0xFFFu) - 1;
                    const float* vc = v + ((size_t)(b * SEQ + g_col_src[b][ci])) * DIM;
                    float p = 0.f;
                    #pragma unroll
                    for (int q = 0; q < DIM; q++) p = fmaf(ur[q], vc[q], p);
                    p = fminf(fmaxf(p, 1e-8f), 1.0f - 1e-8f);
                    corr += __logf(1.0f - p) - __logf(p);
                    c = g_cnext[b][ci];
                }
            }
        }
        #pragma unroll
        for (int o = 16; o; o >>= 1) corr += __shfl_xor_sync(0xffffffffu, corr, o);
        if ((tid & 31) == 0 && corr != 0.f) atomicAdd(&g_numer, (double)corr);
        return;
    }

    // ---------- GEMM path: 128x128 tile, single-pass bf16 mma.sync ----------
    const int b    = blockIdx.z - 1;
    const int nr   = g_nrows[b];
    const int nc   = g_ncols[b];
    const int row0 = blockIdx.y * 128;
    const int col0 = blockIdx.x * 128;
    if (row0 >= nr || col0 >= nc) return;

    // warp tiling: 2 (M) x 4 (N) warps; warp tile 64x32
    const int wm = wid & 1, wn = wid >> 1;
    const int m_base = wm * 64, n_base = wn * 32;

    const uint32_t aH = smem_u32(sAh) +
        (uint32_t)(((m_base + (lane & 15)) * SR2 + ((lane >> 4) << 3)) * 2);
    const uint32_t bH = smem_u32(sBh) +
        (uint32_t)(((n_base + (lane & 7)) * SR2 + (((lane >> 3) & 1) << 3)) * 2);

    // staging: bf16 direct copy (rows compacted & contiguous)
    const int rr = tid >> 1;
    const int hf = (tid & 1) << 4;   // 0 or 16 bf16 within 32-chunk
    const __nv_bfloat16* uR = &g_ub[b][row0 + rr][hf];
    const __nv_bfloat16* vR = &g_vb[b][col0 + rr][hf];

    float acc[4][4][4];
    #pragma unroll
    for (int mi = 0; mi < 4; mi++)
        #pragma unroll
        for (int ni = 0; ni < 4; ni++)
            #pragma unroll
            for (int q = 0; q < 4; q++) acc[mi][ni][q] = 0.f;

    #pragma unroll
    for (int kc = 0; kc < 2; kc++) {
        {
            const int base = rr * SR2 + hf;
            ((uint4*)(&sAh[base]))[0] = ((const uint4*)(uR + kc * 32))[0];
            ((uint4*)(&sAh[base]))[1] = ((const uint4*)(uR + kc * 32))[1];
            ((uint4*)(&sBh[base]))[0] = ((const uint4*)(vR + kc * 32))[0];
            ((uint4*)(&sBh[base]))[1] = ((const uint4*)(vR + kc * 32))[1];
        }
        __syncthreads();

        #pragma unroll
        for (int kk = 0; kk < 2; kk++) {
            const uint32_t koff = (uint32_t)(kk * 16 * 2);
            uint32_t ah[4][4], bh[4][2];
            #pragma unroll
            for (int mi = 0; mi < 4; mi++)
                ldmatrix_x4(ah[mi], aH + (uint32_t)((mi * 16 * SR2) * 2) + koff);
            #pragma unroll
            for (int ni = 0; ni < 4; ni++)
                ldmatrix_x2(bh[ni], bH + (uint32_t)((ni * 8 * SR2) * 2) + koff);
            #pragma unroll
            for (int mi = 0; mi < 4; mi++)
                #pragma unroll
                for (int ni = 0; ni < 4; ni++)
                    mma_bf16(acc[mi][ni], ah[mi], bh[ni]);
        }
        __syncthreads();
    }

    // ---- epilogue: -log(1-p) over valid pairs, 8 values per __logf ----
    const int rq = lane >> 2;
    const int cq = (lane & 3) << 1;
    float lsum = 0.f;
    #pragma unroll
    for (int mi = 0; mi < 4; mi++) {
        const int rA = row0 + m_base + mi * 16 + rq;
        #pragma unroll
        for (int np = 0; np < 2; np++) {
            float prod = 1.0f;
            #pragma unroll
            for (int nj = 0; nj < 2; nj++) {
                const int ni = np * 2 + nj;
                const int cA = col0 + n_base + ni * 8 + cq;
                #pragma unroll
                for (int q = 0; q < 4; q++) {
                    const int r = rA + ((q >> 1) << 3);
                    const int c = cA + (q & 1);
                    float p = acc[mi][ni][q];
                    p = fminf(fmaxf(p, 1e-8f), 1.0f - 1e-8f);
                    const float x = (r < nr && c < nc) ? (1.0f - p) : 1.0f;
                    prod *= x;
                }
            }
            lsum -= __logf(prod);
        }
    }
    #pragma unroll
    for (int o = 16; o; o >>= 1) lsum += __shfl_xor_sync(0xffffffffu, lsum, o);
    if (lane == 0) wsum[wid] = lsum;
    __syncthreads();
    if (wid == 0) {
        float s = (lane < 8) ? wsum[lane] : 0.f;
        #pragma unroll
        for (int o = 4; o; o >>= 1) s += __shfl_xor_sync(0xffffffffu, s, o);
        if (lane == 0) atomicAdd(&g_numer, (double)s);
    }
}

// ---------------- finalize: result + state reset (1 block; epochs cover chains)
__global__ void finalize_kernel(float* __restrict__ out, int n) {
    __shared__ double s_res;
    if (threadIdx.x == 0) {
        double denom = 0.0;
        #pragma unroll
        for (int q = 0; q < BATCH; q++)
            denom += (double)g_nrows[q] * (double)g_ncols[q];
        s_res = g_numer / (denom + 1e-8);
        g_numer = 0.0;
        #pragma unroll
        for (int q = 0; q < BATCH; q++) { g_nrows[q] = 0; g_ncols[q] = 0; }
        g_epoch = g_epoch + 1;
    }
    __syncthreads();
    float r = (float)s_res;
    for (int i = threadIdx.x; i < n; i += blockDim.x) out[i] = r;
}

// ---------------- launch ------------------------------------------------------
extern "C" void kernel_launch(void* const* d_in, const int* in_sizes, int n_in,
                              void* d_out, int out_size) {
    const int*           ids  = (const int*)d_in[0];
    const unsigned char* tf   = (const unsigned char*)d_in[1];
    const unsigned char* act  = (const unsigned char*)d_in[2];
    const int*           keys = (const int*)d_in[3];
    const float*         u    = (const float*)d_in[4];
    const float*         v    = (const float*)d_in[5];
    const int M = in_sizes[3];

    prep_kernel<<<64, 256>>>(ids, tf, act, u, v);
    dim3 grid(SEQ / 128, SEQ / 128, BATCH + 1);   // z==0 -> correction blocks
    main_kernel<<<grid, 256>>>(u, v, keys, M);
    finalize_kernel<<<1, 256>>>((float*)d_out, out_size);
}

// round 13
// speedup vs baseline: 1.2551x; 1.0842x over previous
#include <cuda_runtime.h>
#include <cuda_bf16.h>
#include <cstdint>

#define BATCH 8
#define SEQ   2048
#define DIM   64
#define PAIR_BASE 20000
#define SR2   40   // bf16 smem row pitch per 32-K chunk (32 + 8 pad; 80B rows, 16B aligned)

// ---------------- device scratch (static globals: allocation-free) ----------
__device__ int      g_row_src[BATCH][SEQ];
__device__ int      g_col_src[BATCH][SEQ];
__device__ int      g_row_id[BATCH][SEQ];
__device__ unsigned g_chead[BATCH][PAIR_BASE];   // epoch-tagged: (epoch<<12)|(idx+1)
__device__ unsigned g_cnext[BATCH][SEQ];         // epoch-tagged next
__device__ int      g_nrows[BATCH];              // zero at load; reset by finalize
__device__ int      g_ncols[BATCH];
__device__ double   g_numer;                     // zero at load; reset by finalize
__device__ unsigned g_epoch = 1;                 // bumped by finalize each launch

__device__ __forceinline__ uint32_t smem_u32(const void* p) {
    uint32_t a;
    asm("{ .reg .u64 t; cvta.to.shared.u64 t, %1; cvt.u32.u64 %0, t; }" : "=r"(a) : "l"(p));
    return a;
}
__device__ __forceinline__ void ldmatrix_x4(uint32_t* r, uint32_t addr) {
    asm volatile("ldmatrix.sync.aligned.m8n8.x4.shared.b16 {%0,%1,%2,%3}, [%4];"
        : "=r"(r[0]), "=r"(r[1]), "=r"(r[2]), "=r"(r[3]) : "r"(addr));
}
// NON-trans x2: with B stored [n][k], lane l gets Bmem[row=l/4][col=(l%4)*2+e]
// == exactly the mma.m16n8k16 col-major B fragment (n=t/4, k=(t%4)*2+e).
__device__ __forceinline__ void ldmatrix_x2(uint32_t* r, uint32_t addr) {
    asm volatile("ldmatrix.sync.aligned.m8n8.x2.shared.b16 {%0,%1}, [%2];"
        : "=r"(r[0]), "=r"(r[1]) : "r"(addr));
}
__device__ __forceinline__ void mma_bf16(float* c, const uint32_t* a, const uint32_t* b) {
    asm volatile("mma.sync.aligned.m16n8k16.row.col.f32.bf16.bf16.f32 "
        "{%0,%1,%2,%3}, {%4,%5,%6,%7}, {%8,%9}, {%0,%1,%2,%3};"
        : "+f"(c[0]), "+f"(c[1]), "+f"(c[2]), "+f"(c[3])
        : "r"(a[0]), "r"(a[1]), "r"(a[2]), "r"(a[3]), "r"(b[0]), "r"(b[1]));
}

// ---------------- prep: index compaction + epoch-tagged chains ---------------
// 128 blocks x 128 threads (latency-bound: spread over more SMs)
__global__ void prep_kernel(const int* __restrict__ ids,
                            const unsigned char* __restrict__ tf,
                            const unsigned char* __restrict__ act) {
    const int b  = blockIdx.x >> 4;
    const int s  = ((blockIdx.x & 15) << 7) + threadIdx.x;
    const int gs = b * SEQ + s;
    const int id = ids[gs];
    const unsigned lane = threadIdx.x & 31;
    const unsigned below = (1u << lane) - 1u;
    const unsigned epoch = g_epoch;

    const bool ht = tf[gs] != 0;
    const unsigned mt = __ballot_sync(0xffffffffu, ht);
    int baset = 0;
    if (lane == 0 && mt) baset = atomicAdd(&g_nrows[b], __popc(mt));
    baset = __shfl_sync(0xffffffffu, baset, 0);
    if (ht) {
        int i = baset + __popc(mt & below);
        g_row_src[b][i] = s;
        g_row_id[b][i]  = id;
    }

    const bool ha = act[gs] != 0;
    const unsigned ma = __ballot_sync(0xffffffffu, ha);
    int basea = 0;
    if (lane == 0 && ma) basea = atomicAdd(&g_ncols[b], __popc(ma));
    basea = __shfl_sync(0xffffffffu, basea, 0);
    if (ha) {
        int i = basea + __popc(ma & below);
        g_col_src[b][i] = s;
        g_cnext[b][i]   = atomicExch(&g_chead[b][id], (epoch << 12) | (unsigned)(i + 1));
    }
}

// ---------------- main: correction (z==0) + bf16 HMMA GEMM (z>=1) -----------
__global__ __launch_bounds__(256, 2)
void main_kernel(const float* __restrict__ u, const float* __restrict__ v,
                 const int* __restrict__ keys, int M) {
    __shared__ __align__(16) __nv_bfloat16 sAh[128 * SR2];
    __shared__ __align__(16) __nv_bfloat16 sBh[128 * SR2];
    __shared__ float wsum[8];

    const int tid  = threadIdx.x;
    const int wid  = tid >> 5;
    const int lane = tid & 31;

    if (blockIdx.z == 0) {
        // ---------- correction: rare positives get [-log p + log(1-p)] ----------
        const int cb    = blockIdx.y * 16 + blockIdx.x;   // 0..255
        const int b     = cb & 7;
        const int chunk = cb >> 3;                        // 0..31
        const int nr    = g_nrows[b];
        const int r     = chunk + (tid << 5);
        const unsigned epoch = g_epoch;
        float corr = 0.f;
        if (r < nr) {
            const int rid    = g_row_id[b][r];
            const int lo_key = rid * PAIR_BASE;
            const int hi_key = lo_key + PAIR_BASE;
            int lo = 0, hi = M;
            while (lo < hi) {
                int mid = (lo + hi) >> 1;
                if (__ldg(&keys[mid]) < lo_key) lo = mid + 1; else hi = mid;
            }
            const float* ur = u + ((size_t)(b * SEQ + g_row_src[b][r])) * DIM;
            int prev = -1;
            for (int i = lo; i < M; i++) {
                const int k = __ldg(&keys[i]);
                if (k >= hi_key) break;
                if (k == prev) continue;     // set semantics (duplicate keys)
                prev = k;
                unsigned c = g_chead[b][k - lo_key];
                while ((c >> 12) == epoch) {   // stale-epoch value terminates chain
                    const int ci = (int)(c & 0xFFFu) - 1;
                    const float* vc = v + ((size_t)(b * SEQ + g_col_src[b][ci])) * DIM;
                    float p = 0.f;
                    #pragma unroll
                    for (int q = 0; q < DIM; q++) p = fmaf(ur[q], vc[q], p);
                    p = fminf(fmaxf(p, 1e-8f), 1.0f - 1e-8f);
                    corr += __logf(1.0f - p) - __logf(p);
                    c = g_cnext[b][ci];
                }
            }
        }
        #pragma unroll
        for (int o = 16; o; o >>= 1) corr += __shfl_xor_sync(0xffffffffu, corr, o);
        if ((tid & 31) == 0 && corr != 0.f) atomicAdd(&g_numer, (double)corr);
        return;
    }

    // ---------- GEMM path: 128x128 tile, single-pass bf16 mma.sync ----------
    const int b    = blockIdx.z - 1;
    const int nr   = g_nrows[b];
    const int nc   = g_ncols[b];
    const int row0 = blockIdx.y * 128;
    const int col0 = blockIdx.x * 128;
    if (row0 >= nr || col0 >= nc) return;

    // warp tiling: 2 (M) x 4 (N) warps; warp tile 64x32
    const int wm = wid & 1, wn = wid >> 1;
    const int m_base = wm * 64, n_base = wn * 32;

    const uint32_t aH = smem_u32(sAh) +
        (uint32_t)(((m_base + (lane & 15)) * SR2 + ((lane >> 4) << 3)) * 2);
    const uint32_t bH = smem_u32(sBh) +
        (uint32_t)(((n_base + (lane & 7)) * SR2 + (((lane >> 3) & 1) << 3)) * 2);

    // staging pointers (stale rows beyond nr/nc are in-bounds; masked in epilogue)
    const int rr = tid >> 1;
    const int hf = (tid & 1) << 4;   // 0 or 16 floats within 32-chunk
    const float* uR = u + ((size_t)(b * SEQ + g_row_src[b][row0 + rr])) * DIM + hf;
    const float* vR = v + ((size_t)(b * SEQ + g_col_src[b][col0 + rr])) * DIM + hf;

    float acc[4][4][4];
    #pragma unroll
    for (int mi = 0; mi < 4; mi++)
        #pragma unroll
        for (int ni = 0; ni < 4; ni++)
            #pragma unroll
            for (int q = 0; q < 4; q++) acc[mi][ni][q] = 0.f;

    #pragma unroll
    for (int kc = 0; kc < 2; kc++) {
        // ---- stage chunk kc: convert fp32 -> bf16 tiles ----
        {
            const int base = rr * SR2 + hf;
            __nv_bfloat162* da = (__nv_bfloat162*)(&sAh[base]);
            __nv_bfloat162* db = (__nv_bfloat162*)(&sBh[base]);
            #pragma unroll
            for (int q = 0; q < 4; q++) {
                float4 a = ((const float4*)(uR + kc * 32))[q];
                da[2*q]   = __floats2bfloat162_rn(a.x, a.y);
                da[2*q+1] = __floats2bfloat162_rn(a.z, a.w);
                float4 c = ((const float4*)(vR + kc * 32))[q];
                db[2*q]   = __floats2bfloat162_rn(c.x, c.y);
                db[2*q+1] = __floats2bfloat162_rn(c.z, c.w);
            }
        }
        __syncthreads();

        #pragma unroll
        for (int kk = 0; kk < 2; kk++) {
            const uint32_t koff = (uint32_t)(kk * 16 * 2);
            uint32_t ah[4][4], bh[4][2];
            #pragma unroll
            for (int mi = 0; mi < 4; mi++)
                ldmatrix_x4(ah[mi], aH + (uint32_t)((mi * 16 * SR2) * 2) + koff);
            #pragma unroll
            for (int ni = 0; ni < 4; ni++)
                ldmatrix_x2(bh[ni], bH + (uint32_t)((ni * 8 * SR2) * 2) + koff);
            #pragma unroll
            for (int mi = 0; mi < 4; mi++)
                #pragma unroll
                for (int ni = 0; ni < 4; ni++)
                    mma_bf16(acc[mi][ni], ah[mi], bh[ni]);
        }
        __syncthreads();
    }

    // ---- epilogue: -log(1-p) over valid pairs, 8 values per __logf ----
    const int rq = lane >> 2;
    const int cq = (lane & 3) << 1;
    float lsum = 0.f;
    #pragma unroll
    for (int mi = 0; mi < 4; mi++) {
        const int rA = row0 + m_base + mi * 16 + rq;
        #pragma unroll
        for (int np = 0; np < 2; np++) {
            float prod = 1.0f;
            #pragma unroll
            for (int nj = 0; nj < 2; nj++) {
                const int ni = np * 2 + nj;
                const int cA = col0 + n_base + ni * 8 + cq;
                #pragma unroll
                for (int q = 0; q < 4; q++) {
                    const int r = rA + ((q >> 1) << 3);
                    const int c = cA + (q & 1);
                    float p = acc[mi][ni][q];
                    p = fminf(fmaxf(p, 1e-8f), 1.0f - 1e-8f);
                    const float x = (r < nr && c < nc) ? (1.0f - p) : 1.0f;
                    prod *= x;
                }
            }
            lsum -= __logf(prod);
        }
    }
    #pragma unroll
    for (int o = 16; o; o >>= 1) lsum += __shfl_xor_sync(0xffffffffu, lsum, o);
    if (lane == 0) wsum[wid] = lsum;
    __syncthreads();
    if (wid == 0) {
        float s = (lane < 8) ? wsum[lane] : 0.f;
        #pragma unroll
        for (int o = 4; o; o >>= 1) s += __shfl_xor_sync(0xffffffffu, s, o);
        if (lane == 0) atomicAdd(&g_numer, (double)s);
    }
}

// ---------------- finalize: result + state reset (1 block; epochs cover chains)
__global__ void finalize_kernel(float* __restrict__ out, int n) {
    __shared__ double s_res;
    if (threadIdx.x == 0) {
        double denom = 0.0;
        #pragma unroll
        for (int q = 0; q < BATCH; q++)
            denom += (double)g_nrows[q] * (double)g_ncols[q];
        s_res = g_numer / (denom + 1e-8);
        g_numer = 0.0;
        #pragma unroll
        for (int q = 0; q < BATCH; q++) { g_nrows[q] = 0; g_ncols[q] = 0; }
        g_epoch = g_epoch + 1;
    }
    __syncthreads();
    float r = (float)s_res;
    for (int i = threadIdx.x; i < n; i += blockDim.x) out[i] = r;
}

// ---------------- launch ------------------------------------------------------
extern "C" void kernel_launch(void* const* d_in, const int* in_sizes, int n_in,
                              void* d_out, int out_size) {
    const int*           ids  = (const int*)d_in[0];
    const unsigned char* tf   = (const unsigned char*)d_in[1];
    const unsigned char* act  = (const unsigned char*)d_in[2];
    const int*           keys = (const int*)d_in[3];
    const float*         u    = (const float*)d_in[4];
    const float*         v    = (const float*)d_in[5];
    const int M = in_sizes[3];

    prep_kernel<<<128, 128>>>(ids, tf, act);
    dim3 grid(SEQ / 128, SEQ / 128, BATCH + 1);   // z==0 -> correction blocks
    main_kernel<<<grid, 256>>>(u, v, keys, M);
    finalize_kernel<<<1, 256>>>((float*)d_out, out_size);
}